// round 3
// baseline (speedup 1.0000x reference)
#include <cuda_runtime.h>
#include <cstdint>

typedef unsigned long long ull;

#define TILE_M   128
#define NTHREADS 512
#define LDE      514          // padded row length (floats) of e_s[d][k]

#define X_ELEMS   (64*128)    // floats
#define E_ELEMS   (64*LDE)    // floats
// smem: x (32768B) + e (131584B) + t1(512B) + t2(2048B) + ind(512B) + lred(128B)
#define SMEM_BYTES (X_ELEMS*4 + E_ELEMS*4 + 128*4 + 512*4 + 128*4 + 16*8)

__device__ double g_loss_sum;

__global__ void vq_zero_kernel() { g_loss_sum = 0.0; }

__device__ __forceinline__ ull ffma2(ull a, ull b, ull c) {
    ull d;
    asm("fma.rn.f32x2 %0, %1, %2, %3;" : "=l"(d) : "l"(a), "l"(b), "l"(c));
    return d;
}
__device__ __forceinline__ float lo32(ull u) { return __uint_as_float((unsigned)u); }
__device__ __forceinline__ float hi32(ull u) { return __uint_as_float((unsigned)(u >> 32)); }
__device__ __forceinline__ ull   dupf(float v) {
    ull r;
    asm("mov.b64 %0, {%1, %1};" : "=l"(r) : "f"(v));
    return r;
}

__global__ __launch_bounds__(NTHREADS, 1)
void vq_main_kernel(const float* __restrict__ lat,
                    const float* __restrict__ emb,
                    float* __restrict__ out)
{
    extern __shared__ unsigned char smem_raw[];
    float*  x_s   = (float*)smem_raw;              // [d][r]       64*128
    float*  e_s   = x_s + X_ELEMS;                 // [d][k] ld=LDE
    float*  t1_s  = e_s + E_ELEMS;                 // [128]
    float*  t2_s  = t1_s + 128;                    // [512]
    int*    ind_s = (int*)(t2_s + 512);            // [128]
    double* lred  = (double*)(ind_s + 128);        // [16]

    const int tid  = threadIdx.x;
    const int wid  = tid >> 5;      // 0..15 : row-group (8 rows each)
    const int lane = tid & 31;      // 0..31 : code lane
    const int n0   = blockIdx.x * TILE_M;
    const int b    = n0 >> 12;                      // n0 / 4096
    const int p0   = n0 & 4095;
    const float* xg = lat + ((size_t)b << 18) + p0; // lat[b][0][p0]

    // ---- load x tile [d][r], coalesced over r ----
    for (int i = tid; i < 64 * 128; i += NTHREADS) {
        int d = i >> 7, r = i & 127;
        x_s[i] = __ldg(&xg[(d << 12) + r]);
    }
    // ---- load emb transposed into e_s[d*LDE + k], coalesced over d ----
    for (int i = tid; i < 512 * 64; i += NTHREADS) {
        int k = i >> 6, d = i & 63;
        e_s[d * LDE + k] = __ldg(&emb[i]);
    }
    __syncthreads();

    // ---- t1[r] = sequential fp32 sum of fl(x_d^2), d ascending (replicates ref) ----
    if (tid < 128) {
        float acc = 0.0f;
        #pragma unroll 1
        for (int d = 0; d < 64; ++d) {
            float v = x_s[(d << 7) + tid];
            acc = __fadd_rn(acc, __fmul_rn(v, v));
        }
        t1_s[tid] = acc;
    }
    // ---- t2[k] = sequential fp32 sum of fl(e_d^2) ----
    {
        float acc = 0.0f;
        #pragma unroll 1
        for (int d = 0; d < 64; ++d) {
            float v = e_s[d * LDE + tid];
            acc = __fadd_rn(acc, __fmul_rn(v, v));
        }
        t2_s[tid] = acc;
    }
    __syncthreads();

    // ---- main GEMM + argmin ----
    // warp wid owns rows wid*8..wid*8+7 (as 4 f32x2 row-pairs);
    // lane owns codes {chunk*128 + lane + 32*j, j=0..3}, 4 chunks.
    float t1r[8];
    ull   ukey[8];
    #pragma unroll
    for (int i = 0; i < 8; ++i) { t1r[i] = t1_s[wid * 8 + i]; ukey[i] = ~0ull; }

    const float* xp = x_s + wid * 8;

    #pragma unroll 1
    for (int chunk = 0; chunk < 4; ++chunk) {
        const int kb = chunk * 128 + lane;
        ull acc[4][4];
        #pragma unroll
        for (int p = 0; p < 4; ++p)
            #pragma unroll
            for (int j = 0; j < 4; ++j)
                acc[p][j] = 0ull;

        const float* ep = e_s + kb;

        #pragma unroll 2
        for (int d = 0; d < 64; ++d) {
            ull xv[4];                 // row pairs (2p, 2p+1) — warp-uniform broadcast
            #pragma unroll
            for (int p = 0; p < 4; ++p)
                xv[p] = *(const ull*)(xp + (d << 7) + 2 * p);
            ull ed[4];
            #pragma unroll
            for (int j = 0; j < 4; ++j)
                ed[j] = dupf(ep[d * LDE + 32 * j]);
            #pragma unroll
            for (int p = 0; p < 4; ++p)
                #pragma unroll
                for (int j = 0; j < 4; ++j)
                    acc[p][j] = ffma2(xv[p], ed[j], acc[p][j]);
        }

        // epilogue: dist = fl( fl(t1 + t2) - 2*m ), keep running packed min
        #pragma unroll
        for (int j = 0; j < 4; ++j) {
            const int k = kb + 32 * j;
            const float t2k = t2_s[k];
            #pragma unroll
            for (int p = 0; p < 4; ++p) {
                float m0 = lo32(acc[p][j]);          // row 2p
                float m1 = hi32(acc[p][j]);          // row 2p+1
                float d0 = __fsub_rn(__fadd_rn(t1r[2 * p],     t2k), 2.0f * m0);
                float d1 = __fsub_rn(__fadd_rn(t1r[2 * p + 1], t2k), 2.0f * m1);
                ull u0 = ((ull)__float_as_uint(d0) << 32) | (unsigned)k;
                ull u1 = ((ull)__float_as_uint(d1) << 32) | (unsigned)k;
                if (u0 < ukey[2 * p])     ukey[2 * p]     = u0;
                if (u1 < ukey[2 * p + 1]) ukey[2 * p + 1] = u1;
            }
        }
    }

    // ---- warp-wide argmin reduction (32 lanes hold mins over disjoint code sets) ----
    #pragma unroll
    for (int i = 0; i < 8; ++i) {
        ull best = ukey[i];
        #pragma unroll
        for (int off = 16; off > 0; off >>= 1) {
            ull o = __shfl_xor_sync(0xffffffffu, best, off);
            if (o < best) best = o;
        }
        if (lane == 0)
            ind_s[wid * 8 + i] = (int)(best & 0xffffffffu);  // min dist, ties -> min k
    }
    __syncthreads();

    // ---- gather + straight-through output + loss partial ----
    float lsum = 0.0f;
    const size_t obase = ((size_t)b << 18) + p0;
    for (int i = tid; i < 64 * 128; i += NTHREADS) {
        int d = i >> 7, r = i & 127;
        float e = e_s[d * LDE + ind_s[r]];
        float x = x_s[i];
        float qm = __fsub_rn(e, x);                              // fl(q - lat)
        out[obase + ((size_t)d << 12) + r] = __fadd_rn(x, qm);   // fl(lat + fl(q-lat))
        lsum = fmaf(qm, qm, lsum);
    }
    // block-reduce loss -> one double atomic per CTA
    #pragma unroll
    for (int off = 16; off > 0; off >>= 1)
        lsum += __shfl_xor_sync(0xffffffffu, lsum, off);
    if (lane == 0) lred[wid] = (double)lsum;
    __syncthreads();
    if (wid == 0) {
        double s = (lane < 16) ? lred[lane] : 0.0;
        #pragma unroll
        for (int off = 8; off > 0; off >>= 1)
            s += __shfl_xor_sync(0xffffffffu, s, off);
        if (lane == 0)
            atomicAdd(&g_loss_sum, s);
    }
}

__global__ void vq_fin_kernel(float* __restrict__ out, long long numel, long long loss_idx)
{
    float lm = (float)(g_loss_sum / (double)numel);
    // vq_loss = fl( fl(lm*0.25) + lm )
    out[loss_idx] = __fadd_rn(__fmul_rn(lm, 0.25f), lm);
}

extern "C" void kernel_launch(void* const* d_in, const int* in_sizes, int n_in,
                              void* d_out, int out_size)
{
    const float* lat = (const float*)d_in[0];
    const float* emb = (const float*)d_in[1];
    float* out = (float*)d_out;

    const long long numel = (long long)in_sizes[0];     // 8388608
    const int n_rows = (int)(numel / 64);               // 131072
    const int grid   = n_rows / TILE_M;                 // 1024

    cudaFuncSetAttribute(vq_main_kernel,
                         cudaFuncAttributeMaxDynamicSharedMemorySize, SMEM_BYTES);

    vq_zero_kernel<<<1, 1>>>();
    vq_main_kernel<<<grid, NTHREADS, SMEM_BYTES>>>(lat, emb, out);

    long long loss_idx = (out_size > numel) ? numel : (long long)out_size - 1;
    vq_fin_kernel<<<1, 1>>>(out, numel, loss_idx);
}